// round 4
// baseline (speedup 1.0000x reference)
#include <cuda_runtime.h>
#include <math.h>

#define SEQ   128
#define BATCH 32
#define TB    4096      // SEQ*BATCH rows
#define HID   1024
#define VOC   32000

// ---------------- scratch (device globals; no allocation allowed) -------------
__device__ float g_x [TB * HID];          // gathered embeddings / layer input
__device__ float g_xw[TB * HID];          // precomputed input projection
__device__ float g_y0[TB * HID];          // layer-0 outputs [t][b][h]
__device__ float g_y1[TB * HID];          // layer-1 outputs [t][b][h]
__device__ float g_hT[2 * BATCH * HID];   // ping-pong transposed hidden [k][b]

// ---------------- embedding gather -------------------------------------------
__global__ void k_gather(const int* __restrict__ idx, const float* __restrict__ emb,
                         float* __restrict__ out) {
    int r = blockIdx.x;                       // row = t*BATCH + b
    int token = __ldg(&idx[r]);
    const float4* src = reinterpret_cast<const float4*>(emb + (size_t)token * HID);
    float4* dst = reinterpret_cast<float4*>(out + (size_t)r * HID);
    dst[threadIdx.x] = src[threadIdx.x];      // 256 threads * float4 = 1024 floats
}

// ---------------- SGEMM: C[M,N] = A[M,K] @ B[N,K]^T + bias[N] ----------------
// Both A and B are row-major with K contiguous. 128x128 tile, 8x8 per thread.
#define BM 128
#define BN 128
#define BKK 16
__global__ __launch_bounds__(256)
void k_sgemm_bias(const float* __restrict__ A, const float* __restrict__ B,
                  const float* __restrict__ bias, float* __restrict__ C,
                  int M, int N, int K) {
    __shared__ float As[BKK][BM + 4];
    __shared__ float Bs[BKK][BN + 4];
    const int bm = blockIdx.y * BM;
    const int bn = blockIdx.x * BN;
    const int tid = threadIdx.x;
    const int tr = tid >> 4;      // 0..15  (row group)
    const int tc = tid & 15;      // 0..15  (col group)
    float acc[8][8];
    #pragma unroll
    for (int i = 0; i < 8; i++)
        #pragma unroll
        for (int j = 0; j < 8; j++) acc[i][j] = 0.f;

    for (int k0 = 0; k0 < K; k0 += BKK) {
        #pragma unroll
        for (int i = 0; i < 2; i++) {
            int v = tid + i * 256;            // 0..511 float4 slots
            int r = v >> 2;                   // 0..127
            int kk = (v & 3) << 2;            // 0,4,8,12
            float4 fa = *reinterpret_cast<const float4*>(&A[(size_t)(bm + r) * K + k0 + kk]);
            As[kk + 0][r] = fa.x; As[kk + 1][r] = fa.y;
            As[kk + 2][r] = fa.z; As[kk + 3][r] = fa.w;
            float4 fb = *reinterpret_cast<const float4*>(&B[(size_t)(bn + r) * K + k0 + kk]);
            Bs[kk + 0][r] = fb.x; Bs[kk + 1][r] = fb.y;
            Bs[kk + 2][r] = fb.z; Bs[kk + 3][r] = fb.w;
        }
        __syncthreads();
        #pragma unroll
        for (int k = 0; k < BKK; k++) {
            float ra[8], rb[8];
            *reinterpret_cast<float4*>(&ra[0]) = *reinterpret_cast<float4*>(&As[k][tr * 8]);
            *reinterpret_cast<float4*>(&ra[4]) = *reinterpret_cast<float4*>(&As[k][tr * 8 + 4]);
            *reinterpret_cast<float4*>(&rb[0]) = *reinterpret_cast<float4*>(&Bs[k][tc * 8]);
            *reinterpret_cast<float4*>(&rb[4]) = *reinterpret_cast<float4*>(&Bs[k][tc * 8 + 4]);
            #pragma unroll
            for (int i = 0; i < 8; i++)
                #pragma unroll
                for (int j = 0; j < 8; j++)
                    acc[i][j] += ra[i] * rb[j];
        }
        __syncthreads();
    }
    #pragma unroll
    for (int i = 0; i < 8; i++) {
        int row = bm + tr * 8 + i;
        #pragma unroll
        for (int j = 0; j < 8; j += 4) {
            int col = bn + tc * 8 + j;
            float4 o;
            o.x = acc[i][j + 0] + __ldg(&bias[col + 0]);
            o.y = acc[i][j + 1] + __ldg(&bias[col + 1]);
            o.z = acc[i][j + 2] + __ldg(&bias[col + 2]);
            o.w = acc[i][j + 3] + __ldg(&bias[col + 3]);
            *reinterpret_cast<float4*>(&C[(size_t)row * N + col]) = o;
        }
    }
}

// ---------------- hidden transpose: h[b][k] -> hT[k][b] ----------------------
__global__ void k_transpose_h(const float* __restrict__ h, float* __restrict__ hT) {
    int b = blockIdx.x;        // 32
    int k = threadIdx.x;       // 1024
    hT[k * BATCH + b] = h[b * HID + k];
}

// ---------------- one recurrence step ----------------------------------------
// y[b][j] = tanh(xw_t[b][j] + sum_k h[b][k]*Whh[j][k] + bhh[j])
// h is read k-major (hT_prev[k][b]); warp = one j; lane -> (b-quad, k-phase).
__global__ __launch_bounds__(256)
void k_rnn_step(const float* __restrict__ xw_t,    // [32][1024]
                const float* __restrict__ Whh,     // [1024][1024]
                const float* __restrict__ bhh,     // [1024]
                const float* __restrict__ hT_prev, // [1024][32]
                float* __restrict__ hT_cur,        // [1024][32]
                float* __restrict__ y_t) {         // [32][1024]
    __shared__ float h_s[128 * 32];                // one k-tile, [k_local][b]
    const int tid  = threadIdx.x;
    const int w    = tid >> 5;                     // warp -> j offset
    const int lane = tid & 31;
    const int bq   = (lane & 7) << 2;              // b base: 0,4,...,28
    const int kq   = lane >> 3;                    // k phase 0..3
    const int j    = blockIdx.x * 8 + w;
    const float* wrow = Whh + (size_t)j * HID;
    float4 acc = make_float4(0.f, 0.f, 0.f, 0.f);

    for (int kt = 0; kt < 8; kt++) {
        const float4* src = reinterpret_cast<const float4*>(hT_prev + kt * 4096);
        float4* dst = reinterpret_cast<float4*>(h_s);
        #pragma unroll
        for (int i = 0; i < 4; i++) dst[tid + i * 256] = src[tid + i * 256];
        __syncthreads();
        const float* wr = wrow + kt * 128;
        #pragma unroll
        for (int ki = 0; ki < 32; ki++) {
            int kl = (ki << 2) + kq;               // warp covers 4 consecutive k
            float wv = __ldg(&wr[kl]);
            float4 hv = *reinterpret_cast<const float4*>(&h_s[(kl << 5) + bq]);
            acc.x += hv.x * wv; acc.y += hv.y * wv;
            acc.z += hv.z * wv; acc.w += hv.w * wv;
        }
        __syncthreads();
    }
    // reduce the 4 k-phases (lane bits 3,4)
    acc.x += __shfl_xor_sync(0xffffffffu, acc.x, 8);
    acc.y += __shfl_xor_sync(0xffffffffu, acc.y, 8);
    acc.z += __shfl_xor_sync(0xffffffffu, acc.z, 8);
    acc.w += __shfl_xor_sync(0xffffffffu, acc.w, 8);
    acc.x += __shfl_xor_sync(0xffffffffu, acc.x, 16);
    acc.y += __shfl_xor_sync(0xffffffffu, acc.y, 16);
    acc.z += __shfl_xor_sync(0xffffffffu, acc.z, 16);
    acc.w += __shfl_xor_sync(0xffffffffu, acc.w, 16);

    if (kq == 0) {
        float bj = __ldg(&bhh[j]);
        float4 o;
        o.x = tanhf(acc.x + __ldg(&xw_t[(bq + 0) * HID + j]) + bj);
        o.y = tanhf(acc.y + __ldg(&xw_t[(bq + 1) * HID + j]) + bj);
        o.z = tanhf(acc.z + __ldg(&xw_t[(bq + 2) * HID + j]) + bj);
        o.w = tanhf(acc.w + __ldg(&xw_t[(bq + 3) * HID + j]) + bj);
        *reinterpret_cast<float4*>(&hT_cur[(j << 5) + bq]) = o;   // next-step layout
        y_t[(bq + 0) * HID + j] = o.x;                            // normal layout
        y_t[(bq + 1) * HID + j] = o.y;
        y_t[(bq + 2) * HID + j] = o.z;
        y_t[(bq + 3) * HID + j] = o.w;
    }
}

// ---------------- in-place row log_softmax ------------------------------------
__global__ void k_logsoftmax(float* __restrict__ logits) {
    extern __shared__ float row[];                 // 32000 floats
    __shared__ float red[33];
    const int tid = threadIdx.x;
    float* p = logits + (size_t)blockIdx.x * VOC;

    float mx = -INFINITY;
    for (int i = tid; i < VOC / 4; i += 256) {
        float4 v = reinterpret_cast<const float4*>(p)[i];
        reinterpret_cast<float4*>(row)[i] = v;
        mx = fmaxf(mx, fmaxf(fmaxf(v.x, v.y), fmaxf(v.z, v.w)));
    }
    #pragma unroll
    for (int o = 16; o; o >>= 1) mx = fmaxf(mx, __shfl_xor_sync(0xffffffffu, mx, o));
    if ((tid & 31) == 0) red[tid >> 5] = mx;
    __syncthreads();
    if (tid < 32) {
        float m = (tid < 8) ? red[tid] : -INFINITY;
        #pragma unroll
        for (int o = 4; o; o >>= 1) m = fmaxf(m, __shfl_xor_sync(0xffffffffu, m, o));
        if (tid == 0) red[32] = m;
    }
    __syncthreads();
    mx = red[32];

    float s = 0.f;
    for (int i = tid; i < VOC; i += 256) s += __expf(row[i] - mx);
    #pragma unroll
    for (int o = 16; o; o >>= 1) s += __shfl_xor_sync(0xffffffffu, s, o);
    if ((tid & 31) == 0) red[tid >> 5] = s;
    __syncthreads();
    if (tid < 32) {
        float t2 = (tid < 8) ? red[tid] : 0.f;
        #pragma unroll
        for (int o = 4; o; o >>= 1) t2 += __shfl_xor_sync(0xffffffffu, t2, o);
        if (tid == 0) red[32] = t2;
    }
    __syncthreads();
    float lse = mx + logf(red[32]);

    for (int i = tid; i < VOC / 4; i += 256) {
        float4 v = reinterpret_cast<float4*>(row)[i];
        float4 o = make_float4(v.x - lse, v.y - lse, v.z - lse, v.w - lse);
        reinterpret_cast<float4*>(p)[i] = o;
    }
}

// ---------------- final hidden copy -------------------------------------------
__global__ void k_copy_hidden(const float* __restrict__ y0, const float* __restrict__ y1,
                              float* __restrict__ outh) {
    int i = blockIdx.x * 256 + threadIdx.x;        // 32768 threads
    outh[i]               = y0[(SEQ - 1) * BATCH * HID + i];
    outh[BATCH * HID + i] = y1[(SEQ - 1) * BATCH * HID + i];
}

// ---------------- launch --------------------------------------------------------
extern "C" void kernel_launch(void* const* d_in, const int* in_sizes, int n_in,
                              void* d_out, int out_size) {
    const int*   input_x = (const int*)  d_in[0];
    const float* hidden  = (const float*)d_in[1];
    const float* emb     = (const float*)d_in[2];
    const float* W_ih    = (const float*)d_in[3];
    const float* W_hh    = (const float*)d_in[4];
    const float* b_ih    = (const float*)d_in[5];
    const float* b_hh    = (const float*)d_in[6];
    const float* W_out   = (const float*)d_in[7];
    const float* b_out   = (const float*)d_in[8];
    float* out = (float*)d_out;

    // One-time host-side setup (deterministic; avoids repeated driver calls
    // during graph capture).
    static float *x = nullptr, *xw, *y0, *y1, *hT;
    if (!x) {
        cudaGetSymbolAddress((void**)&x,  g_x);
        cudaGetSymbolAddress((void**)&xw, g_xw);
        cudaGetSymbolAddress((void**)&y0, g_y0);
        cudaGetSymbolAddress((void**)&y1, g_y1);
        cudaGetSymbolAddress((void**)&hT, g_hT);
        cudaFuncSetAttribute(k_logsoftmax,
                             cudaFuncAttributeMaxDynamicSharedMemorySize, VOC * 4);
    }
    float* hTb[2] = {hT, hT + BATCH * HID};

    k_gather<<<TB, 256>>>(input_x, emb, x);

    dim3 gsmall(HID / BN, TB / BM);   // (8, 32)
    for (int l = 0; l < 2; l++) {
        const float* A = (l == 0) ? x : y0;
        float* y = (l == 0) ? y0 : y1;
        k_sgemm_bias<<<gsmall, 256>>>(A, W_ih + (size_t)l * HID * HID,
                                      b_ih + l * HID, xw, TB, HID, HID);
        k_transpose_h<<<BATCH, HID>>>(hidden + l * BATCH * HID, hTb[0]);
        for (int t = 0; t < SEQ; t++) {
            k_rnn_step<<<128, 256>>>(xw + (size_t)t * BATCH * HID,
                                     W_hh + (size_t)l * HID * HID,
                                     b_hh + l * HID,
                                     hTb[t & 1], hTb[(t + 1) & 1],
                                     y + (size_t)t * BATCH * HID);
        }
    }

    dim3 gbig(VOC / BN, TB / BM);     // (250, 32)
    k_sgemm_bias<<<gbig, 256>>>(y1, W_out, b_out, out, TB, VOC, HID);

    k_logsoftmax<<<TB, 256, VOC * 4>>>(out);

    long long hid_off = (long long)TB * VOC;
    if ((long long)out_size >= hid_off + 2LL * BATCH * HID) {
        k_copy_hidden<<<BATCH * HID / 256, 256>>>(y0, y1, out + hid_off);
    }
}

// round 5
// speedup vs baseline: 1.1247x; 1.1247x over previous
#include <cuda_runtime.h>
#include <math.h>

#define SEQ   128
#define BATCH 32
#define TB    4096      // SEQ*BATCH rows
#define HID   1024
#define VOC   32000
#define NBLK  128       // persistent grid size (<=148 -> fully co-resident)

// ---------------- scratch (device globals; no allocation allowed) -------------
__device__ float g_x [TB * HID];          // gathered embeddings / layer input
__device__ float g_xw[TB * HID];          // precomputed input projection
__device__ float g_y0[TB * HID];          // layer-0 outputs [t][b][h]
__device__ float g_y1[TB * HID];          // layer-1 outputs [t][b][h]
__device__ float g_hT[2 * BATCH * HID];   // ping-pong transposed hidden [j][b]

// software grid barrier state (reset before each persistent launch)
__device__ unsigned g_bar_cnt;
__device__ volatile unsigned g_bar_flag;

__global__ void k_bar_reset() { g_bar_cnt = 0; g_bar_flag = 0; }

__device__ __forceinline__ void grid_sync(unsigned target_epoch) {
    __syncthreads();
    if (threadIdx.x == 0) {
        __threadfence();                                   // publish our writes
        unsigned arrived = atomicAdd(&g_bar_cnt, 1u) + 1u;
        if (arrived == target_epoch * NBLK) {
            g_bar_flag = target_epoch;                     // release (volatile st)
        } else {
            while (g_bar_flag < target_epoch) { }          // volatile ld spins in L2
        }
        __threadfence();
    }
    __syncthreads();
}

// ---------------- embedding gather -------------------------------------------
__global__ void k_gather(const int* __restrict__ idx, const float* __restrict__ emb,
                         float* __restrict__ out) {
    int r = blockIdx.x;                       // row = t*BATCH + b
    int token = __ldg(&idx[r]);
    const float4* src = reinterpret_cast<const float4*>(emb + (size_t)token * HID);
    float4* dst = reinterpret_cast<float4*>(out + (size_t)r * HID);
    dst[threadIdx.x] = src[threadIdx.x];      // 256 threads * float4 = 1024 floats
}

// ---------------- SGEMM: C[M,N] = A[M,K] @ B[N,K]^T + bias[N] ----------------
#define BM 128
#define BN 128
#define BKK 16
__global__ __launch_bounds__(256)
void k_sgemm_bias(const float* __restrict__ A, const float* __restrict__ B,
                  const float* __restrict__ bias, float* __restrict__ C,
                  int M, int N, int K) {
    __shared__ float As[BKK][BM + 4];
    __shared__ float Bs[BKK][BN + 4];
    const int bm = blockIdx.y * BM;
    const int bn = blockIdx.x * BN;
    const int tid = threadIdx.x;
    const int tr = tid >> 4;
    const int tc = tid & 15;
    float acc[8][8];
    #pragma unroll
    for (int i = 0; i < 8; i++)
        #pragma unroll
        for (int j = 0; j < 8; j++) acc[i][j] = 0.f;

    for (int k0 = 0; k0 < K; k0 += BKK) {
        #pragma unroll
        for (int i = 0; i < 2; i++) {
            int v = tid + i * 256;
            int r = v >> 2;
            int kk = (v & 3) << 2;
            float4 fa = *reinterpret_cast<const float4*>(&A[(size_t)(bm + r) * K + k0 + kk]);
            As[kk + 0][r] = fa.x; As[kk + 1][r] = fa.y;
            As[kk + 2][r] = fa.z; As[kk + 3][r] = fa.w;
            float4 fb = *reinterpret_cast<const float4*>(&B[(size_t)(bn + r) * K + k0 + kk]);
            Bs[kk + 0][r] = fb.x; Bs[kk + 1][r] = fb.y;
            Bs[kk + 2][r] = fb.z; Bs[kk + 3][r] = fb.w;
        }
        __syncthreads();
        #pragma unroll
        for (int k = 0; k < BKK; k++) {
            float ra[8], rb[8];
            *reinterpret_cast<float4*>(&ra[0]) = *reinterpret_cast<float4*>(&As[k][tr * 8]);
            *reinterpret_cast<float4*>(&ra[4]) = *reinterpret_cast<float4*>(&As[k][tr * 8 + 4]);
            *reinterpret_cast<float4*>(&rb[0]) = *reinterpret_cast<float4*>(&Bs[k][tc * 8]);
            *reinterpret_cast<float4*>(&rb[4]) = *reinterpret_cast<float4*>(&Bs[k][tc * 8 + 4]);
            #pragma unroll
            for (int i = 0; i < 8; i++)
                #pragma unroll
                for (int j = 0; j < 8; j++)
                    acc[i][j] += ra[i] * rb[j];
        }
        __syncthreads();
    }
    #pragma unroll
    for (int i = 0; i < 8; i++) {
        int row = bm + tr * 8 + i;
        #pragma unroll
        for (int j = 0; j < 8; j += 4) {
            int col = bn + tc * 8 + j;
            float4 o;
            o.x = acc[i][j + 0] + __ldg(&bias[col + 0]);
            o.y = acc[i][j + 1] + __ldg(&bias[col + 1]);
            o.z = acc[i][j + 2] + __ldg(&bias[col + 2]);
            o.w = acc[i][j + 3] + __ldg(&bias[col + 3]);
            *reinterpret_cast<float4*>(&C[(size_t)row * N + col]) = o;
        }
    }
}

// ---------------- hidden transpose: h[b][k] -> hT[k][b] ----------------------
__global__ void k_transpose_h(const float* __restrict__ h, float* __restrict__ hT) {
    int b = blockIdx.x;        // 32
    int k = threadIdx.x;       // 1024
    hT[k * BATCH + b] = h[b * HID + k];
}

// ---------------- persistent recurrence: all 128 steps of one layer -----------
// Block bx owns j in [bx*8, bx*8+8). W_hh slice cached in smem ONCE.
// Per step: warp w covers k-range [w*128, w*128+128), lanes = batch.
// h state ping-pongs in global [j][b] layout; read with __ldcg (L1 incoherent
// across SMs within one launch). Grid barrier between steps.
__global__ __launch_bounds__(256)
void k_rnn_persist(const float* __restrict__ xw,    // [SEQ][32][1024]
                   const float* __restrict__ Whh,   // [1024][1024] layer slice
                   const float* __restrict__ bhh,   // [1024]
                   float* __restrict__ hT,          // [2][1024*32] ping-pong, buf0=init
                   float* __restrict__ y) {         // [SEQ][32][1024]
    __shared__ float Ws[8][HID];                    // 32 KB
    __shared__ float red[8][8][32];                 // [warp][j][b], 8 KB
    __shared__ float bias_s[8];
    const int tid  = threadIdx.x;
    const int w    = tid >> 5;
    const int lane = tid & 31;
    const int j0   = blockIdx.x * 8;

    {   // load W slice once: 8*1024 floats = 2048 float4 / 256 threads
        const float4* src = reinterpret_cast<const float4*>(Whh + (size_t)j0 * HID);
        float4* dst = reinterpret_cast<float4*>(&Ws[0][0]);
        #pragma unroll
        for (int i = 0; i < 8; i++) dst[tid + 256 * i] = src[tid + 256 * i];
        if (tid < 8) bias_s[tid] = bhh[j0 + tid];
    }
    __syncthreads();

    const int kbase = w * 128;
    unsigned epoch = 0;

    for (int t = 0; t < SEQ; t++) {
        const float* hp = hT + (size_t)(t & 1) * (HID * BATCH);
        float*       hn = hT + (size_t)((t + 1) & 1) * (HID * BATCH);

        float acc[8];
        #pragma unroll
        for (int j = 0; j < 8; j++) acc[j] = 0.f;

        #pragma unroll 4
        for (int kg = 0; kg < 128; kg += 8) {
            float hv[8];
            #pragma unroll
            for (int u = 0; u < 8; u++)
                hv[u] = __ldcg(&hp[(kbase + kg + u) * BATCH + lane]);
            #pragma unroll
            for (int j = 0; j < 8; j++) {
                float4 w0 = *reinterpret_cast<const float4*>(&Ws[j][kbase + kg]);
                float4 w1 = *reinterpret_cast<const float4*>(&Ws[j][kbase + kg + 4]);
                acc[j] += hv[0] * w0.x + hv[1] * w0.y + hv[2] * w0.z + hv[3] * w0.w
                        + hv[4] * w1.x + hv[5] * w1.y + hv[6] * w1.z + hv[7] * w1.w;
            }
        }

        #pragma unroll
        for (int j = 0; j < 8; j++) red[w][j][lane] = acc[j];
        __syncthreads();

        {   // reduce 8 k-chunks; thread -> (j = tid/32, b = tid%32)
            const int j = tid >> 5, b = tid & 31;
            float s = red[0][j][b] + red[1][j][b] + red[2][j][b] + red[3][j][b]
                    + red[4][j][b] + red[5][j][b] + red[6][j][b] + red[7][j][b];
            s += __ldg(&xw[(size_t)t * (BATCH * HID) + b * HID + (j0 + j)]) + bias_s[j];
            float v = tanhf(s);
            hn[(j0 + j) * BATCH + b] = v;                              // next state
            y[(size_t)t * (BATCH * HID) + b * HID + (j0 + j)] = v;     // layer output
        }
        epoch++;
        grid_sync(epoch);
    }
}

// ---------------- in-place row log_softmax ------------------------------------
__global__ void k_logsoftmax(float* __restrict__ logits) {
    extern __shared__ float row[];                 // 32000 floats
    __shared__ float red[33];
    const int tid = threadIdx.x;
    float* p = logits + (size_t)blockIdx.x * VOC;

    float mx = -INFINITY;
    for (int i = tid; i < VOC / 4; i += 256) {
        float4 v = reinterpret_cast<const float4*>(p)[i];
        reinterpret_cast<float4*>(row)[i] = v;
        mx = fmaxf(mx, fmaxf(fmaxf(v.x, v.y), fmaxf(v.z, v.w)));
    }
    #pragma unroll
    for (int o = 16; o; o >>= 1) mx = fmaxf(mx, __shfl_xor_sync(0xffffffffu, mx, o));
    if ((tid & 31) == 0) red[tid >> 5] = mx;
    __syncthreads();
    if (tid < 32) {
        float m = (tid < 8) ? red[tid] : -INFINITY;
        #pragma unroll
        for (int o = 4; o; o >>= 1) m = fmaxf(m, __shfl_xor_sync(0xffffffffu, m, o));
        if (tid == 0) red[32] = m;
    }
    __syncthreads();
    mx = red[32];

    float s = 0.f;
    for (int i = tid; i < VOC; i += 256) s += __expf(row[i] - mx);
    #pragma unroll
    for (int o = 16; o; o >>= 1) s += __shfl_xor_sync(0xffffffffu, s, o);
    if ((tid & 31) == 0) red[tid >> 5] = s;
    __syncthreads();
    if (tid < 32) {
        float t2 = (tid < 8) ? red[tid] : 0.f;
        #pragma unroll
        for (int o = 4; o; o >>= 1) t2 += __shfl_xor_sync(0xffffffffu, t2, o);
        if (tid == 0) red[32] = t2;
    }
    __syncthreads();
    float lse = mx + logf(red[32]);

    for (int i = tid; i < VOC / 4; i += 256) {
        float4 v = reinterpret_cast<float4*>(row)[i];
        float4 o = make_float4(v.x - lse, v.y - lse, v.z - lse, v.w - lse);
        reinterpret_cast<float4*>(p)[i] = o;
    }
}

// ---------------- final hidden copy -------------------------------------------
__global__ void k_copy_hidden(const float* __restrict__ y0, const float* __restrict__ y1,
                              float* __restrict__ outh) {
    int i = blockIdx.x * 256 + threadIdx.x;        // 32768 threads
    outh[i]               = y0[(SEQ - 1) * BATCH * HID + i];
    outh[BATCH * HID + i] = y1[(SEQ - 1) * BATCH * HID + i];
}

// ---------------- launch --------------------------------------------------------
extern "C" void kernel_launch(void* const* d_in, const int* in_sizes, int n_in,
                              void* d_out, int out_size) {
    const int*   input_x = (const int*)  d_in[0];
    const float* hidden  = (const float*)d_in[1];
    const float* emb     = (const float*)d_in[2];
    const float* W_ih    = (const float*)d_in[3];
    const float* W_hh    = (const float*)d_in[4];
    const float* b_ih    = (const float*)d_in[5];
    const float* b_hh    = (const float*)d_in[6];
    const float* W_out   = (const float*)d_in[7];
    const float* b_out   = (const float*)d_in[8];
    float* out = (float*)d_out;

    static float *x = nullptr, *xw, *y0, *y1, *hT;
    if (!x) {
        cudaGetSymbolAddress((void**)&x,  g_x);
        cudaGetSymbolAddress((void**)&xw, g_xw);
        cudaGetSymbolAddress((void**)&y0, g_y0);
        cudaGetSymbolAddress((void**)&y1, g_y1);
        cudaGetSymbolAddress((void**)&hT, g_hT);
        cudaFuncSetAttribute(k_logsoftmax,
                             cudaFuncAttributeMaxDynamicSharedMemorySize, VOC * 4);
    }

    k_gather<<<TB, 256>>>(input_x, emb, x);

    dim3 gsmall(HID / BN, TB / BM);   // (8, 32)
    for (int l = 0; l < 2; l++) {
        const float* A = (l == 0) ? x : y0;
        float* y = (l == 0) ? y0 : y1;
        k_sgemm_bias<<<gsmall, 256>>>(A, W_ih + (size_t)l * HID * HID,
                                      b_ih + l * HID, xw, TB, HID, HID);
        k_transpose_h<<<BATCH, HID>>>(hidden + l * BATCH * HID, hT);   // buf0
        k_bar_reset<<<1, 1>>>();
        k_rnn_persist<<<NBLK, 256>>>(xw, W_hh + (size_t)l * HID * HID,
                                     b_hh + l * HID, hT, y);
    }

    dim3 gbig(VOC / BN, TB / BM);     // (250, 32)
    k_sgemm_bias<<<gbig, 256>>>(y1, W_out, b_out, out, TB, VOC, HID);

    k_logsoftmax<<<TB, 256, VOC * 4>>>(out);

    long long hid_off = (long long)TB * VOC;
    if ((long long)out_size >= hid_off + 2LL * BATCH * HID) {
        k_copy_hidden<<<BATCH * HID / 256, 256>>>(y0, y1, out + hid_off);
    }
}

// round 7
// speedup vs baseline: 1.4669x; 1.3043x over previous
#include <cuda_runtime.h>
#include <math.h>
#include <stdint.h>

#define SEQ   128
#define BATCH 32
#define TB    4096      // SEQ*BATCH rows
#define HID   1024
#define VOC   32000
#define NBLK  128       // persistent grid size (<=148 -> fully co-resident)

// ---------------- scratch (device globals; no allocation allowed) -------------
__device__ float g_x [TB * HID];
__device__ float g_xw[TB * HID];
__device__ float g_y0[TB * HID];
__device__ float g_y1[TB * HID];
__device__ float g_hT[2 * BATCH * HID];   // ping-pong transposed hidden [j][b]

__device__ unsigned g_bar_cnt;
__device__ volatile unsigned g_bar_flag;

__global__ void k_bar_reset() { g_bar_cnt = 0; g_bar_flag = 0; }

__device__ __forceinline__ void grid_sync(unsigned target_epoch) {
    __syncthreads();
    if (threadIdx.x == 0) {
        __threadfence();
        unsigned arrived = atomicAdd(&g_bar_cnt, 1u) + 1u;
        if (arrived == target_epoch * NBLK) {
            g_bar_flag = target_epoch;
        } else {
            while (g_bar_flag < target_epoch) { }
        }
        __threadfence();
    }
    __syncthreads();
}

__device__ __forceinline__ float tf32r(float x) {
    float y;
    asm("cvt.rna.tf32.f32 %0, %1;" : "=f"(y) : "f"(x));
    return y;
}

// ---------------- embedding gather -------------------------------------------
__global__ void k_gather(const int* __restrict__ idx, const float* __restrict__ emb,
                         float* __restrict__ out) {
    int r = blockIdx.x;
    int token = __ldg(&idx[r]);
    const float4* src = reinterpret_cast<const float4*>(emb + (size_t)token * HID);
    float4* dst = reinterpret_cast<float4*>(out + (size_t)r * HID);
    dst[threadIdx.x] = src[threadIdx.x];
}

// ---------------- TF32 tensor-core GEMM: C = A[M,K] @ B[N,K]^T + bias --------
// Block 128x128x32, 8 warps, warp tile 64x32 as 4x4 m16n8k8 mma.sync.
#define BM 128
#define BN 128
#define BK 32
__global__ __launch_bounds__(256)
void k_tf32gemm_bias(const float* __restrict__ A, const float* __restrict__ B,
                     const float* __restrict__ bias, float* __restrict__ C,
                     int M, int N, int K) {
    __shared__ float As[BM][BK + 1];
    __shared__ float Bs[BN][BK + 1];
    const int bm = blockIdx.y * BM;
    const int bn = blockIdx.x * BN;
    const int tid  = threadIdx.x;
    const int wid  = tid >> 5;
    const int lane = tid & 31;
    const int wr = wid >> 2;          // 0..1  warp row (64 rows)
    const int wc = wid & 3;           // 0..3  warp col (32 cols)
    const int lr = lane >> 2;         // 0..7
    const int lc = lane & 3;          // 0..3

    float acc[4][4][4];
    #pragma unroll
    for (int mi = 0; mi < 4; mi++)
        #pragma unroll
        for (int ni = 0; ni < 4; ni++)
            #pragma unroll
            for (int e = 0; e < 4; e++) acc[mi][ni][e] = 0.f;

    for (int k0 = 0; k0 < K; k0 += BK) {
        // fill As/Bs: 4096 floats each; 256 thr * 16 floats (4x float4), tf32-rounded
        #pragma unroll
        for (int i = 0; i < 4; i++) {
            int s = tid + i * 256;          // 0..1023 float4 slots
            int r = s >> 3;                 // 0..127
            int kk = (s & 7) << 2;          // 0,4,...,28
            float4 fa = *reinterpret_cast<const float4*>(&A[(size_t)(bm + r) * K + k0 + kk]);
            As[r][kk + 0] = tf32r(fa.x); As[r][kk + 1] = tf32r(fa.y);
            As[r][kk + 2] = tf32r(fa.z); As[r][kk + 3] = tf32r(fa.w);
            float4 fb = *reinterpret_cast<const float4*>(&B[(size_t)(bn + r) * K + k0 + kk]);
            Bs[r][kk + 0] = tf32r(fb.x); Bs[r][kk + 1] = tf32r(fb.y);
            Bs[r][kk + 2] = tf32r(fb.z); Bs[r][kk + 3] = tf32r(fb.w);
        }
        __syncthreads();

        #pragma unroll
        for (int ks = 0; ks < BK; ks += 8) {
            uint32_t af[4][4];
            #pragma unroll
            for (int mi = 0; mi < 4; mi++) {
                int rb = wr * 64 + mi * 16;
                af[mi][0] = __float_as_uint(As[rb + lr    ][ks + lc    ]);
                af[mi][1] = __float_as_uint(As[rb + lr + 8][ks + lc    ]);
                af[mi][2] = __float_as_uint(As[rb + lr    ][ks + lc + 4]);
                af[mi][3] = __float_as_uint(As[rb + lr + 8][ks + lc + 4]);
            }
            uint32_t bf[4][2];
            #pragma unroll
            for (int ni = 0; ni < 4; ni++) {
                int nb = wc * 32 + ni * 8;
                bf[ni][0] = __float_as_uint(Bs[nb + lr][ks + lc    ]);
                bf[ni][1] = __float_as_uint(Bs[nb + lr][ks + lc + 4]);
            }
            #pragma unroll
            for (int mi = 0; mi < 4; mi++)
                #pragma unroll
                for (int ni = 0; ni < 4; ni++) {
                    asm volatile(
                        "mma.sync.aligned.m16n8k8.row.col.f32.tf32.tf32.f32 "
                        "{%0,%1,%2,%3}, {%4,%5,%6,%7}, {%8,%9}, {%0,%1,%2,%3};"
                        : "+f"(acc[mi][ni][0]), "+f"(acc[mi][ni][1]),
                          "+f"(acc[mi][ni][2]), "+f"(acc[mi][ni][3])
                        : "r"(af[mi][0]), "r"(af[mi][1]), "r"(af[mi][2]), "r"(af[mi][3]),
                          "r"(bf[ni][0]), "r"(bf[ni][1]));
                }
        }
        __syncthreads();
    }

    // epilogue: D layout m16n8: d0,d1 -> (lr, 2*lc+{0,1}); d2,d3 -> (lr+8, ...)
    #pragma unroll
    for (int mi = 0; mi < 4; mi++) {
        #pragma unroll
        for (int ni = 0; ni < 4; ni++) {
            int row = bm + wr * 64 + mi * 16 + lr;
            int col = bn + wc * 32 + ni * 8 + lc * 2;
            float b0 = __ldg(&bias[col]);
            float b1 = __ldg(&bias[col + 1]);
            float2 o0 = make_float2(acc[mi][ni][0] + b0, acc[mi][ni][1] + b1);
            float2 o1 = make_float2(acc[mi][ni][2] + b0, acc[mi][ni][3] + b1);
            *reinterpret_cast<float2*>(&C[(size_t)row * N + col]) = o0;
            *reinterpret_cast<float2*>(&C[(size_t)(row + 8) * N + col]) = o1;
        }
    }
}

// ---------------- hidden transpose: h[b][k] -> hT[k][b] ----------------------
__global__ void k_transpose_h(const float* __restrict__ h, float* __restrict__ hT) {
    int b = blockIdx.x;
    int k = threadIdx.x;
    hT[k * BATCH + b] = h[b * HID + k];
}

// ---------------- persistent recurrence (one layer, 128 steps) ---------------
__global__ __launch_bounds__(256)
void k_rnn_persist(const float* __restrict__ xw,    // [SEQ][32][1024]
                   const float* __restrict__ Whh,   // [1024][1024]
                   const float* __restrict__ bhh,   // [1024]
                   float* __restrict__ hT,          // [2][1024*32] ping-pong
                   float* __restrict__ y) {         // [SEQ][32][1024]
    __shared__ float Ws[8][HID];
    __shared__ float red[8][8][32];
    __shared__ float bias_s[8];
    const int tid  = threadIdx.x;
    const int w    = tid >> 5;
    const int lane = tid & 31;
    const int j0   = blockIdx.x * 8;

    {
        const float4* src = reinterpret_cast<const float4*>(Whh + (size_t)j0 * HID);
        float4* dst = reinterpret_cast<float4*>(&Ws[0][0]);
        #pragma unroll
        for (int i = 0; i < 8; i++) dst[tid + 256 * i] = src[tid + 256 * i];
        if (tid < 8) bias_s[tid] = bhh[j0 + tid];
    }
    __syncthreads();

    const int kbase = w * 128;
    unsigned epoch = 0;

    for (int t = 0; t < SEQ; t++) {
        const float* hp = hT + (size_t)(t & 1) * (HID * BATCH);
        float*       hn = hT + (size_t)((t + 1) & 1) * (HID * BATCH);

        float acc[8];
        #pragma unroll
        for (int j = 0; j < 8; j++) acc[j] = 0.f;

        #pragma unroll 4
        for (int kg = 0; kg < 128; kg += 8) {
            float hv[8];
            #pragma unroll
            for (int u = 0; u < 8; u++)
                hv[u] = __ldcg(&hp[(kbase + kg + u) * BATCH + lane]);
            #pragma unroll
            for (int j = 0; j < 8; j++) {
                float4 w0 = *reinterpret_cast<const float4*>(&Ws[j][kbase + kg]);
                float4 w1 = *reinterpret_cast<const float4*>(&Ws[j][kbase + kg + 4]);
                acc[j] += hv[0] * w0.x + hv[1] * w0.y + hv[2] * w0.z + hv[3] * w0.w
                        + hv[4] * w1.x + hv[5] * w1.y + hv[6] * w1.z + hv[7] * w1.w;
            }
        }

        #pragma unroll
        for (int j = 0; j < 8; j++) red[w][j][lane] = acc[j];
        __syncthreads();

        {
            const int j = tid >> 5, b = tid & 31;
            float s = red[0][j][b] + red[1][j][b] + red[2][j][b] + red[3][j][b]
                    + red[4][j][b] + red[5][j][b] + red[6][j][b] + red[7][j][b];
            s += __ldg(&xw[(size_t)t * (BATCH * HID) + b * HID + (j0 + j)]) + bias_s[j];
            float v = tanhf(s);
            hn[(j0 + j) * BATCH + b] = v;
            y[(size_t)t * (BATCH * HID) + b * HID + (j0 + j)] = v;
        }
        epoch++;
        grid_sync(epoch);
    }
}

// ---------------- in-place row log_softmax ------------------------------------
__global__ void k_logsoftmax(float* __restrict__ logits) {
    extern __shared__ float row[];
    __shared__ float red[33];
    const int tid = threadIdx.x;
    float* p = logits + (size_t)blockIdx.x * VOC;

    float mx = -INFINITY;
    for (int i = tid; i < VOC / 4; i += 256) {
        float4 v = reinterpret_cast<const float4*>(p)[i];
        reinterpret_cast<float4*>(row)[i] = v;
        mx = fmaxf(mx, fmaxf(fmaxf(v.x, v.y), fmaxf(v.z, v.w)));
    }
    #pragma unroll
    for (int o = 16; o; o >>= 1) mx = fmaxf(mx, __shfl_xor_sync(0xffffffffu, mx, o));
    if ((tid & 31) == 0) red[tid >> 5] = mx;
    __syncthreads();
    if (tid < 32) {
        float m = (tid < 8) ? red[tid] : -INFINITY;
        #pragma unroll
        for (int o = 4; o; o >>= 1) m = fmaxf(m, __shfl_xor_sync(0xffffffffu, m, o));
        if (tid == 0) red[32] = m;
    }
    __syncthreads();
    mx = red[32];

    float s = 0.f;
    for (int i = tid; i < VOC; i += 256) s += __expf(row[i] - mx);
    #pragma unroll
    for (int o = 16; o; o >>= 1) s += __shfl_xor_sync(0xffffffffu, s, o);
    if ((tid & 31) == 0) red[tid >> 5] = s;
    __syncthreads();
    if (tid < 32) {
        float t2 = (tid < 8) ? red[tid] : 0.f;
        #pragma unroll
        for (int o = 4; o; o >>= 1) t2 += __shfl_xor_sync(0xffffffffu, t2, o);
        if (tid == 0) red[32] = t2;
    }
    __syncthreads();
    float lse = mx + logf(red[32]);

    for (int i = tid; i < VOC / 4; i += 256) {
        float4 v = reinterpret_cast<float4*>(row)[i];
        float4 o = make_float4(v.x - lse, v.y - lse, v.z - lse, v.w - lse);
        reinterpret_cast<float4*>(p)[i] = o;
    }
}

// ---------------- final hidden copy -------------------------------------------
__global__ void k_copy_hidden(const float* __restrict__ y0, const float* __restrict__ y1,
                              float* __restrict__ outh) {
    int i = blockIdx.x * 256 + threadIdx.x;
    outh[i]               = y0[(SEQ - 1) * BATCH * HID + i];
    outh[BATCH * HID + i] = y1[(SEQ - 1) * BATCH * HID + i];
}

// ---------------- launch --------------------------------------------------------
extern "C" void kernel_launch(void* const* d_in, const int* in_sizes, int n_in,
                              void* d_out, int out_size) {
    const int*   input_x = (const int*)  d_in[0];
    const float* hidden  = (const float*)d_in[1];
    const float* emb     = (const float*)d_in[2];
    const float* W_ih    = (const float*)d_in[3];
    const float* W_hh    = (const float*)d_in[4];
    const float* b_ih    = (const float*)d_in[5];
    const float* b_hh    = (const float*)d_in[6];
    const float* W_out   = (const float*)d_in[7];
    const float* b_out   = (const float*)d_in[8];
    float* out = (float*)d_out;

    static float *x = nullptr, *xw, *y0, *y1, *hT;
    if (!x) {
        cudaGetSymbolAddress((void**)&x,  g_x);
        cudaGetSymbolAddress((void**)&xw, g_xw);
        cudaGetSymbolAddress((void**)&y0, g_y0);
        cudaGetSymbolAddress((void**)&y1, g_y1);
        cudaGetSymbolAddress((void**)&hT, g_hT);
        cudaFuncSetAttribute(k_logsoftmax,
                             cudaFuncAttributeMaxDynamicSharedMemorySize, VOC * 4);
    }

    k_gather<<<TB, 256>>>(input_x, emb, x);

    dim3 gsmall(HID / BN, TB / BM);   // (8, 32)
    for (int l = 0; l < 2; l++) {
        const float* A = (l == 0) ? x : y0;
        float* y = (l == 0) ? y0 : y1;
        k_tf32gemm_bias<<<gsmall, 256>>>(A, W_ih + (size_t)l * HID * HID,
                                         b_ih + l * HID, xw, TB, HID, HID);
        k_transpose_h<<<BATCH, HID>>>(hidden + l * BATCH * HID, hT);
        k_bar_reset<<<1, 1>>>();
        k_rnn_persist<<<NBLK, 256>>>(xw, W_hh + (size_t)l * HID * HID,
                                     b_hh + l * HID, hT, y);
    }

    dim3 gbig(VOC / BN, TB / BM);     // (250, 32)
    k_tf32gemm_bias<<<gbig, 256>>>(y1, W_out, b_out, out, TB, VOC, HID);

    k_logsoftmax<<<TB, 256, VOC * 4>>>(out);

    long long hid_off = (long long)TB * VOC;
    if ((long long)out_size >= hid_off + 2LL * BATCH * HID) {
        k_copy_hidden<<<BATCH * HID / 256, 256>>>(y0, y1, out + hid_off);
    }
}

// round 8
// speedup vs baseline: 2.4020x; 1.6375x over previous
#include <cuda_runtime.h>
#include <math.h>
#include <stdint.h>

#define SEQ   128
#define BATCH 32
#define TB    4096      // SEQ*BATCH rows
#define HID   1024
#define VOC   32000
#define NBLK  128       // persistent grid size (<=148 -> fully co-resident)

// ---------------- scratch (device globals; no allocation allowed) -------------
__device__ float g_x [TB * HID];
__device__ float g_xw[TB * HID];
__device__ float g_y0[TB * HID];
__device__ float g_y1[TB * HID];
__device__ float g_hT[2 * BATCH * HID];   // ping-pong hidden, quad-k layout

__device__ unsigned g_bar_cnt;
__device__ volatile unsigned g_bar_flag;

__global__ void k_bar_reset() { g_bar_cnt = 0; g_bar_flag = 0; }

__device__ __forceinline__ void grid_sync(unsigned target_epoch) {
    __syncthreads();
    if (threadIdx.x == 0) {
        __threadfence();
        unsigned arrived = atomicAdd(&g_bar_cnt, 1u) + 1u;
        if (arrived == target_epoch * NBLK) {
            g_bar_flag = target_epoch;
        } else {
            while (g_bar_flag < target_epoch) { }
        }
        __threadfence();
    }
    __syncthreads();
}

__device__ __forceinline__ float tf32r(float x) {
    float y;
    asm("cvt.rna.tf32.f32 %0, %1;" : "=f"(y) : "f"(x));
    return y;
}

// ---------------- embedding gather -------------------------------------------
__global__ void k_gather(const int* __restrict__ idx, const float* __restrict__ emb,
                         float* __restrict__ out) {
    int r = blockIdx.x;
    int token = __ldg(&idx[r]);
    const float4* src = reinterpret_cast<const float4*>(emb + (size_t)token * HID);
    float4* dst = reinterpret_cast<float4*>(out + (size_t)r * HID);
    dst[threadIdx.x] = src[threadIdx.x];
}

// ---------------- TF32 tensor-core GEMM: C = A[M,K] @ B[N,K]^T + bias --------
// Block 128x128x32, 8 warps, warp tile 64x32 as 4x4 m16n8k8 mma.sync.
// Smem holds operands in mma-fragment layout (vector LDS), reg double-buffer.
#define BM 128
#define BN 128
#define BK 32
#define LPAD 33   // lane dim padded 32->33 (16B/8B units) to spread STS banks
__global__ __launch_bounds__(256)
void k_tf32gemm_bias(const float* __restrict__ A, const float* __restrict__ B,
                     const float* __restrict__ bias, float* __restrict__ C,
                     int M, int N, int K) {
    __shared__ float AsF[8  * 4 * LPAD * 4];   // [mt 0..7][ks 0..3][lane pad][e 0..3]
    __shared__ float BsF[16 * 4 * LPAD * 2];   // [nt 0..15][ks][lane pad][e 0..1]
    const int bm = blockIdx.y * BM;
    const int bn = blockIdx.x * BN;
    const int tid  = threadIdx.x;
    const int wid  = tid >> 5;
    const int lane = tid & 31;
    const int wr = wid >> 2;          // warp row (64 rows)
    const int wc = wid & 3;           // warp col (32 cols)
    const int lr = lane >> 2;
    const int lc = lane & 3;

    // per-thread fill coordinates (4 float4 of A and B per k-tile)
    int frA[4], frB[4], rA[4], kkv[4];
    #pragma unroll
    for (int i = 0; i < 4; i++) {
        int s = tid + i * 256;            // 0..1023 float4 slots
        int r = s >> 3;                   // 0..127 tile row
        int kk = (s & 7) << 2;            // 0,4,...,28
        rA[i] = r; kkv[i] = kk;
        int ks = kk >> 3, ch = (kk >> 2) & 1;
        int mt = r >> 4, rr = r & 15;
        frA[i] = (((mt << 2) + ks) * LPAD + ((rr & 7) << 2)) * 4 + ((rr >> 3) | (ch << 1));
        int nt = r >> 3, nr = r & 7;
        frB[i] = (((nt << 2) + ks) * LPAD + (nr << 2)) * 2 + ch;
    }

    float acc[4][4][4];
    #pragma unroll
    for (int mi = 0; mi < 4; mi++)
        #pragma unroll
        for (int ni = 0; ni < 4; ni++)
            #pragma unroll
            for (int e = 0; e < 4; e++) acc[mi][ni][e] = 0.f;

    float4 pa[4], pb[4];
    #pragma unroll
    for (int i = 0; i < 4; i++) {
        pa[i] = *reinterpret_cast<const float4*>(&A[(size_t)(bm + rA[i]) * K + kkv[i]]);
        pb[i] = *reinterpret_cast<const float4*>(&B[(size_t)(bn + rA[i]) * K + kkv[i]]);
    }

    for (int k0 = 0; k0 < K; k0 += BK) {
        #pragma unroll
        for (int i = 0; i < 4; i++) {
            AsF[frA[i] + 0]  = tf32r(pa[i].x);
            AsF[frA[i] + 4]  = tf32r(pa[i].y);
            AsF[frA[i] + 8]  = tf32r(pa[i].z);
            AsF[frA[i] + 12] = tf32r(pa[i].w);
            BsF[frB[i] + 0]  = tf32r(pb[i].x);
            BsF[frB[i] + 2]  = tf32r(pb[i].y);
            BsF[frB[i] + 4]  = tf32r(pb[i].z);
            BsF[frB[i] + 6]  = tf32r(pb[i].w);
        }
        __syncthreads();
        if (k0 + BK < K) {                 // prefetch next tile; hidden under MMA
            #pragma unroll
            for (int i = 0; i < 4; i++) {
                pa[i] = *reinterpret_cast<const float4*>(
                            &A[(size_t)(bm + rA[i]) * K + k0 + BK + kkv[i]]);
                pb[i] = *reinterpret_cast<const float4*>(
                            &B[(size_t)(bn + rA[i]) * K + k0 + BK + kkv[i]]);
            }
        }
        #pragma unroll
        for (int ks = 0; ks < 4; ks++) {
            float4 af[4]; float2 bf[4];
            #pragma unroll
            for (int mi = 0; mi < 4; mi++)
                af[mi] = *reinterpret_cast<const float4*>(
                    &AsF[((((wr << 2) + mi) * 4 + ks) * LPAD + lane) * 4]);
            #pragma unroll
            for (int ni = 0; ni < 4; ni++)
                bf[ni] = *reinterpret_cast<const float2*>(
                    &BsF[((((wc << 2) + ni) * 4 + ks) * LPAD + lane) * 2]);
            #pragma unroll
            for (int mi = 0; mi < 4; mi++)
                #pragma unroll
                for (int ni = 0; ni < 4; ni++) {
                    asm volatile(
                        "mma.sync.aligned.m16n8k8.row.col.f32.tf32.tf32.f32 "
                        "{%0,%1,%2,%3}, {%4,%5,%6,%7}, {%8,%9}, {%0,%1,%2,%3};"
                        : "+f"(acc[mi][ni][0]), "+f"(acc[mi][ni][1]),
                          "+f"(acc[mi][ni][2]), "+f"(acc[mi][ni][3])
                        : "r"(__float_as_uint(af[mi].x)), "r"(__float_as_uint(af[mi].y)),
                          "r"(__float_as_uint(af[mi].z)), "r"(__float_as_uint(af[mi].w)),
                          "r"(__float_as_uint(bf[ni].x)), "r"(__float_as_uint(bf[ni].y)));
                }
        }
        __syncthreads();
    }

    #pragma unroll
    for (int mi = 0; mi < 4; mi++) {
        #pragma unroll
        for (int ni = 0; ni < 4; ni++) {
            int row = bm + wr * 64 + mi * 16 + lr;
            int col = bn + wc * 32 + ni * 8 + lc * 2;
            float b0 = __ldg(&bias[col]);
            float b1 = __ldg(&bias[col + 1]);
            float2 o0 = make_float2(acc[mi][ni][0] + b0, acc[mi][ni][1] + b1);
            float2 o1 = make_float2(acc[mi][ni][2] + b0, acc[mi][ni][3] + b1);
            *reinterpret_cast<float2*>(&C[(size_t)row * N + col]) = o0;
            *reinterpret_cast<float2*>(&C[(size_t)(row + 8) * N + col]) = o1;
        }
    }
}

// ---------------- hidden transpose: h[b][k] -> quad-k hq[k/4][b][k%4] ---------
__global__ void k_transpose_h(const float* __restrict__ h, float* __restrict__ hq) {
    int b = blockIdx.x;
    int k = threadIdx.x;
    hq[(k >> 2) * (BATCH * 4) + (b << 2) + (k & 3)] = h[b * HID + k];
}

// ---------------- persistent recurrence (one layer, 128 steps) ---------------
__global__ __launch_bounds__(256)
void k_rnn_persist(const float* __restrict__ xw,    // [SEQ][32][1024]
                   const float* __restrict__ Whh,   // [1024][1024]
                   const float* __restrict__ bhh,   // [1024]
                   float* __restrict__ hT,          // [2][1024*32] quad-k ping-pong
                   float* __restrict__ y,           // [SEQ][32][1024]
                   int epoch_base) {
    __shared__ float Ws[8][HID];
    __shared__ float red[8][8][32];
    __shared__ float bias_s[8];
    const int tid  = threadIdx.x;
    const int w    = tid >> 5;
    const int lane = tid & 31;
    const int j0   = blockIdx.x * 8;

    {
        const float4* src = reinterpret_cast<const float4*>(Whh + (size_t)j0 * HID);
        float4* dst = reinterpret_cast<float4*>(&Ws[0][0]);
        #pragma unroll
        for (int i = 0; i < 8; i++) dst[tid + 256 * i] = src[tid + 256 * i];
        if (tid < 8) bias_s[tid] = bhh[j0 + tid];
    }
    __syncthreads();

    const int kbase = w * 128;

    for (int t = 0; t < SEQ; t++) {
        const float* hp = hT + (size_t)(t & 1) * (HID * BATCH);
        float*       hn = hT + (size_t)((t + 1) & 1) * (HID * BATCH);

        float acc[8];
        #pragma unroll
        for (int j = 0; j < 8; j++) acc[j] = 0.f;

        #pragma unroll 4
        for (int kg = 0; kg < 128; kg += 8) {
            int q = (kbase + kg) >> 2;
            float4 h0 = __ldcg(reinterpret_cast<const float4*>(&hp[q * 128 + (lane << 2)]));
            float4 h1 = __ldcg(reinterpret_cast<const float4*>(&hp[(q + 1) * 128 + (lane << 2)]));
            #pragma unroll
            for (int j = 0; j < 8; j++) {
                float4 w0 = *reinterpret_cast<const float4*>(&Ws[j][kbase + kg]);
                float4 w1 = *reinterpret_cast<const float4*>(&Ws[j][kbase + kg + 4]);
                acc[j] += h0.x * w0.x + h0.y * w0.y + h0.z * w0.z + h0.w * w0.w
                        + h1.x * w1.x + h1.y * w1.y + h1.z * w1.z + h1.w * w1.w;
            }
        }

        #pragma unroll
        for (int j = 0; j < 8; j++) red[w][j][lane] = acc[j];
        __syncthreads();

        {
            const int j = tid >> 5, b = tid & 31;
            float s = red[0][j][b] + red[1][j][b] + red[2][j][b] + red[3][j][b]
                    + red[4][j][b] + red[5][j][b] + red[6][j][b] + red[7][j][b];
            s += __ldg(&xw[(size_t)t * (BATCH * HID) + b * HID + (j0 + j)]) + bias_s[j];
            float v = tanhf(s);
            int jj = j0 + j;
            hn[(jj >> 2) * 128 + (b << 2) + (jj & 3)] = v;
            y[(size_t)t * (BATCH * HID) + b * HID + jj] = v;
        }
        grid_sync((unsigned)(epoch_base + t + 1));
    }
}

// ---------------- in-place row log_softmax ------------------------------------
__global__ void k_logsoftmax(float* __restrict__ logits) {
    extern __shared__ float row[];
    __shared__ float red[33];
    const int tid = threadIdx.x;
    float* p = logits + (size_t)blockIdx.x * VOC;

    float mx = -INFINITY;
    for (int i = tid; i < VOC / 4; i += 256) {
        float4 v = reinterpret_cast<const float4*>(p)[i];
        reinterpret_cast<float4*>(row)[i] = v;
        mx = fmaxf(mx, fmaxf(fmaxf(v.x, v.y), fmaxf(v.z, v.w)));
    }
    #pragma unroll
    for (int o = 16; o; o >>= 1) mx = fmaxf(mx, __shfl_xor_sync(0xffffffffu, mx, o));
    if ((tid & 31) == 0) red[tid >> 5] = mx;
    __syncthreads();
    if (tid < 32) {
        float m = (tid < 8) ? red[tid] : -INFINITY;
        #pragma unroll
        for (int o = 4; o; o >>= 1) m = fmaxf(m, __shfl_xor_sync(0xffffffffu, m, o));
        if (tid == 0) red[32] = m;
    }
    __syncthreads();
    mx = red[32];

    float s = 0.f;
    for (int i = tid; i < VOC; i += 256) s += __expf(row[i] - mx);
    #pragma unroll
    for (int o = 16; o; o >>= 1) s += __shfl_xor_sync(0xffffffffu, s, o);
    if ((tid & 31) == 0) red[tid >> 5] = s;
    __syncthreads();
    if (tid < 32) {
        float t2 = (tid < 8) ? red[tid] : 0.f;
        #pragma unroll
        for (int o = 4; o; o >>= 1) t2 += __shfl_xor_sync(0xffffffffu, t2, o);
        if (tid == 0) red[32] = t2;
    }
    __syncthreads();
    float lse = mx + logf(red[32]);

    for (int i = tid; i < VOC / 4; i += 256) {
        float4 v = reinterpret_cast<float4*>(row)[i];
        float4 o = make_float4(v.x - lse, v.y - lse, v.z - lse, v.w - lse);
        reinterpret_cast<float4*>(p)[i] = o;
    }
}

// ---------------- final hidden copy -------------------------------------------
__global__ void k_copy_hidden(const float* __restrict__ y0, const float* __restrict__ y1,
                              float* __restrict__ outh) {
    int i = blockIdx.x * 256 + threadIdx.x;
    outh[i]               = y0[(SEQ - 1) * BATCH * HID + i];
    outh[BATCH * HID + i] = y1[(SEQ - 1) * BATCH * HID + i];
}

// ---------------- launch --------------------------------------------------------
extern "C" void kernel_launch(void* const* d_in, const int* in_sizes, int n_in,
                              void* d_out, int out_size) {
    const int*   input_x = (const int*)  d_in[0];
    const float* hidden  = (const float*)d_in[1];
    const float* emb     = (const float*)d_in[2];
    const float* W_ih    = (const float*)d_in[3];
    const float* W_hh    = (const float*)d_in[4];
    const float* b_ih    = (const float*)d_in[5];
    const float* b_hh    = (const float*)d_in[6];
    const float* W_out   = (const float*)d_in[7];
    const float* b_out   = (const float*)d_in[8];
    float* out = (float*)d_out;

    static float *x = nullptr, *xw, *y0, *y1, *hT;
    if (!x) {
        cudaGetSymbolAddress((void**)&x,  g_x);
        cudaGetSymbolAddress((void**)&xw, g_xw);
        cudaGetSymbolAddress((void**)&y0, g_y0);
        cudaGetSymbolAddress((void**)&y1, g_y1);
        cudaGetSymbolAddress((void**)&hT, g_hT);
        cudaFuncSetAttribute(k_logsoftmax,
                             cudaFuncAttributeMaxDynamicSharedMemorySize, VOC * 4);
    }

    k_bar_reset<<<1, 1>>>();          // launch 1
    k_gather<<<TB, 256>>>(input_x, emb, x);   // launch 2

    dim3 gsmall(HID / BN, TB / BM);   // (8, 32)
    for (int l = 0; l < 2; l++) {
        const float* A = (l == 0) ? x : y0;
        float* y = (l == 0) ? y0 : y1;
        k_tf32gemm_bias<<<gsmall, 256>>>(A, W_ih + (size_t)l * HID * HID,
                                         b_ih + l * HID, xw, TB, HID, HID);
        k_transpose_h<<<BATCH, HID>>>(hidden + l * BATCH * HID, hT);
        k_rnn_persist<<<NBLK, 256>>>(xw, W_hh + (size_t)l * HID * HID,
                                     b_hh + l * HID, hT, y, l * SEQ);
    }

    dim3 gbig(VOC / BN, TB / BM);     // (250, 32)
    k_tf32gemm_bias<<<gbig, 256>>>(y1, W_out, b_out, out, TB, VOC, HID);

    k_logsoftmax<<<TB, 256, VOC * 4>>>(out);

    long long hid_off = (long long)TB * VOC;
    if ((long long)out_size >= hid_off + 2LL * BATCH * HID) {
        k_copy_hidden<<<BATCH * HID / 256, 256>>>(y0, y1, out + hid_off);
    }
}